// round 1
// baseline (speedup 1.0000x reference)
#include <cuda_runtime.h>
#include <math.h>

#define HH 2048
#define WW 2048
#define NPB (HH*WW)        // 4,194,304 elems per batch
#define BATCH 8
#define BPB 128            // blocks per batch in pass1
#define T1 256             // threads in pass1 block
#define WIN 5

// Scratch (device globals — no allocation allowed in kernel_launch)
__device__ float g_pmax[BATCH*BPB];
__device__ int   g_pidx[BATCH*BPB];
__device__ float g_psum[BATCH*BPB];
__device__ float g_psq [BATCH*BPB];
__device__ int   g_pcnt[BATCH*BPB];
__device__ float g_psr [BATCH];

// ---------------------------------------------------------------------------
// Pass 1: streaming reduction. Per batch: max + argmax (first occurrence),
// and positive-value stats (sum, sumsq, count) over ALL elements.
// ---------------------------------------------------------------------------
__global__ void __launch_bounds__(T1) psr_pass1(const float* __restrict__ resp) {
    const int b = blockIdx.y;
    const float4* __restrict__ p = (const float4*)(resp + (size_t)b * NPB);

    const int tid    = blockIdx.x * T1 + threadIdx.x;
    const int stride = gridDim.x * T1;            // 32768 threads per batch

    float mx = -INFINITY; int mi = 0;
    float s = 0.f, sq = 0.f; int c = 0;

    #pragma unroll 4
    for (int i = tid; i < NPB/4; i += stride) {
        float4 v = p[i];
        const int base = i * 4;
        float a;
        a = v.x; if (a > mx) { mx = a; mi = base + 0; } if (a > 0.f) { s += a; sq = fmaf(a, a, sq); c++; }
        a = v.y; if (a > mx) { mx = a; mi = base + 1; } if (a > 0.f) { s += a; sq = fmaf(a, a, sq); c++; }
        a = v.z; if (a > mx) { mx = a; mi = base + 2; } if (a > 0.f) { s += a; sq = fmaf(a, a, sq); c++; }
        a = v.w; if (a > mx) { mx = a; mi = base + 3; } if (a > 0.f) { s += a; sq = fmaf(a, a, sq); c++; }
    }

    __shared__ float smax[T1];
    __shared__ int   sidx[T1];
    __shared__ float ssum[T1];
    __shared__ float ssq [T1];
    __shared__ int   scnt[T1];

    const int t = threadIdx.x;
    smax[t] = mx; sidx[t] = mi; ssum[t] = s; ssq[t] = sq; scnt[t] = c;
    __syncthreads();

    #pragma unroll
    for (int off = T1/2; off > 0; off >>= 1) {
        if (t < off) {
            float om = smax[t+off]; int oi = sidx[t+off];
            if (om > smax[t] || (om == smax[t] && oi < sidx[t])) { smax[t] = om; sidx[t] = oi; }
            ssum[t] += ssum[t+off];
            ssq [t] += ssq [t+off];
            scnt[t] += scnt[t+off];
        }
        __syncthreads();
    }

    if (t == 0) {
        const int o = b * BPB + blockIdx.x;
        g_pmax[o] = smax[0];
        g_pidx[o] = sidx[0];
        g_psum[o] = ssum[0];
        g_psq [o] = ssq [0];
        g_pcnt[o] = scnt[0];
    }
}

// ---------------------------------------------------------------------------
// Pass 2: one block per batch. Reduce the 128 partials (double accumulation),
// then subtract positive contributions of the 11x11 window around the peak,
// and compute psr for this batch.
// ---------------------------------------------------------------------------
__global__ void __launch_bounds__(BPB) psr_pass2(const float* __restrict__ resp) {
    const int b = blockIdx.x;
    const int t = threadIdx.x;   // 0..127

    __shared__ float  smax[BPB];
    __shared__ int    sidx[BPB];
    __shared__ double ssum[BPB];
    __shared__ double ssq [BPB];
    __shared__ int    scnt[BPB];

    const int o = b * BPB + t;
    smax[t] = g_pmax[o];
    sidx[t] = g_pidx[o];
    ssum[t] = (double)g_psum[o];
    ssq [t] = (double)g_psq [o];
    scnt[t] = g_pcnt[o];
    __syncthreads();

    #pragma unroll
    for (int off = BPB/2; off > 0; off >>= 1) {
        if (t < off) {
            float om = smax[t+off]; int oi = sidx[t+off];
            if (om > smax[t] || (om == smax[t] && oi < sidx[t])) { smax[t] = om; sidx[t] = oi; }
            ssum[t] += ssum[t+off];
            ssq [t] += ssq [t+off];
            scnt[t] += scnt[t+off];
        }
        __syncthreads();
    }

    const float  maxv = smax[0];
    const int    idx  = sidx[0];
    const double tsum = ssum[0];
    const double tsq  = ssq[0];
    const int    tcnt = scnt[0];
    __syncthreads();

    // Window correction: 11x11 = 121 elements, one per thread (t < 121).
    const int cy = idx / WW;
    const int cx = idx % WW;
    double ws = 0.0, wq = 0.0; int wc = 0;
    if (t < (2*WIN+1)*(2*WIN+1)) {
        const int dy = t / (2*WIN+1) - WIN;
        const int dx = t % (2*WIN+1) - WIN;
        const int y = cy + dy, x = cx + dx;
        if (y >= 0 && y < HH && x >= 0 && x < WW) {
            const float v = resp[(size_t)b * NPB + (size_t)y * WW + x];
            if (v > 0.f) { ws = (double)v; wq = (double)v * (double)v; wc = 1; }
        }
    }
    ssum[t] = ws; ssq[t] = wq; scnt[t] = wc;
    __syncthreads();

    #pragma unroll
    for (int off = BPB/2; off > 0; off >>= 1) {
        if (t < off) {
            ssum[t] += ssum[t+off];
            ssq [t] += ssq [t+off];
            scnt[t] += scnt[t+off];
        }
        __syncthreads();
    }

    if (t == 0) {
        const double n  = (double)(tcnt - scnt[0]);
        const double s  = tsum - ssum[0];
        const double q  = tsq  - ssq[0];
        const double mean = s / n;
        const double var  = (q - n * mean * mean) / (n - 1.0);
        const float  stdv = (float)sqrt(var);
        g_psr[b] = (float)((double)maxv - mean) / (stdv + 1e-5f);
    }
}

// ---------------------------------------------------------------------------
// Pass 3: average psr over batch -> scalar output.
// ---------------------------------------------------------------------------
__global__ void psr_pass3(float* __restrict__ out) {
    float acc = 0.f;
    #pragma unroll
    for (int i = 0; i < BATCH; i++) acc += g_psr[i];
    out[0] = acc / (float)BATCH;
}

extern "C" void kernel_launch(void* const* d_in, const int* in_sizes, int n_in,
                              void* d_out, int out_size) {
    const float* resp = (const float*)d_in[0];
    float* out = (float*)d_out;

    dim3 grid1(BPB, BATCH);
    psr_pass1<<<grid1, T1>>>(resp);
    psr_pass2<<<BATCH, BPB>>>(resp);
    psr_pass3<<<1, 1>>>(out);
}

// round 2
// speedup vs baseline: 1.1106x; 1.1106x over previous
#include <cuda_runtime.h>
#include <math.h>

#define HH 2048
#define WW 2048
#define NPB (HH*WW)            // 4,194,304 elems per batch
#define BATCH 8
#define BPB 128                // blocks per batch
#define T1 256                 // threads per block
#define NBLK (BPB*BATCH)       // 1024 total blocks
#define STRIDE (BPB*T1)        // 32768 threads per batch (in float4 units)
#define ITERS (NPB/4/STRIDE)   // 32 float4 loads per thread, exact
#define WIN 5

// Scratch (device globals — no allocation in kernel_launch)
__device__ float g_pmax[NBLK];
__device__ int   g_pidx[NBLK];
__device__ float g_psum[NBLK];
__device__ float g_psq [NBLK];
__device__ int   g_pcnt[NBLK];
__device__ int   g_counter;      // zero-initialized; reset by last block each run

__global__ void __launch_bounds__(T1) psr_fused(const float* __restrict__ resp,
                                                float* __restrict__ out) {
    const int b   = blockIdx.y;
    const int tid = blockIdx.x * T1 + threadIdx.x;       // 0..32767 within batch
    const float4* __restrict__ p = (const float4*)(resp + (size_t)b * NPB) + tid;

    float mx = -INFINITY; int mi = 0;
    float s = 0.f, sq = 0.f; int c = 0;

    #pragma unroll
    for (int kk = 0; kk < ITERS; kk += 8) {
        float4 r[8];
        #pragma unroll
        for (int j = 0; j < 8; j++)
            r[j] = __ldcs(p + (size_t)(kk + j) * STRIDE);   // 8 LDG.128 in flight
        #pragma unroll
        for (int j = 0; j < 8; j++) {
            const int base = (tid + (kk + j) * STRIDE) * 4;
            float a, m;
            a = r[j].x; if (a > mx) { mx = a; mi = base + 0; }
            m = fmaxf(a, 0.f); s += m; sq = fmaf(m, m, sq); c += (a > 0.f);
            a = r[j].y; if (a > mx) { mx = a; mi = base + 1; }
            m = fmaxf(a, 0.f); s += m; sq = fmaf(m, m, sq); c += (a > 0.f);
            a = r[j].z; if (a > mx) { mx = a; mi = base + 2; }
            m = fmaxf(a, 0.f); s += m; sq = fmaf(m, m, sq); c += (a > 0.f);
            a = r[j].w; if (a > mx) { mx = a; mi = base + 3; }
            m = fmaxf(a, 0.f); s += m; sq = fmaf(m, m, sq); c += (a > 0.f);
        }
    }

    // ---- intra-warp reduce (shuffles) ----
    const unsigned FULL = 0xFFFFFFFFu;
    #pragma unroll
    for (int off = 16; off > 0; off >>= 1) {
        float om = __shfl_down_sync(FULL, mx, off);
        int   oi = __shfl_down_sync(FULL, mi, off);
        if (om > mx || (om == mx && oi < mi)) { mx = om; mi = oi; }
        s  += __shfl_down_sync(FULL, s,  off);
        sq += __shfl_down_sync(FULL, sq, off);
        c  += __shfl_down_sync(FULL, c,  off);
    }

    // ---- cross-warp reduce via smem (8 warps) ----
    __shared__ float wmax[8]; __shared__ int widx[8];
    __shared__ float wsum[8]; __shared__ float wsq[8]; __shared__ int wcnt[8];
    const int lane = threadIdx.x & 31;
    const int wid  = threadIdx.x >> 5;
    if (lane == 0) { wmax[wid] = mx; widx[wid] = mi; wsum[wid] = s; wsq[wid] = sq; wcnt[wid] = c; }
    __syncthreads();

    if (wid == 0) {
        mx = (lane < 8) ? wmax[lane] : -INFINITY;
        mi = (lane < 8) ? widx[lane] : 0x7FFFFFFF;
        s  = (lane < 8) ? wsum[lane] : 0.f;
        sq = (lane < 8) ? wsq[lane]  : 0.f;
        c  = (lane < 8) ? wcnt[lane] : 0;
        #pragma unroll
        for (int off = 4; off > 0; off >>= 1) {
            float om = __shfl_down_sync(FULL, mx, off);
            int   oi = __shfl_down_sync(FULL, mi, off);
            if (om > mx || (om == mx && oi < mi)) { mx = om; mi = oi; }
            s  += __shfl_down_sync(FULL, s,  off);
            sq += __shfl_down_sync(FULL, sq, off);
            c  += __shfl_down_sync(FULL, c,  off);
        }
        if (lane == 0) {
            const int o = b * BPB + blockIdx.x;
            g_pmax[o] = mx; g_pidx[o] = mi; g_psum[o] = s; g_psq[o] = sq; g_pcnt[o] = c;
        }
    }

    // ---- last-block-done: finalize in the same kernel ----
    __shared__ int is_last;
    __threadfence();
    __syncthreads();
    if (threadIdx.x == 0) {
        int prev = atomicAdd(&g_counter, 1);
        is_last = (prev == NBLK - 1);
    }
    __syncthreads();
    if (!is_last) return;

    // One warp per batch (8 warps x 32 lanes = 256 threads).
    __shared__ float spsr[8];
    {
        const int w = threadIdx.x >> 5;     // batch
        const int l = threadIdx.x & 31;

        float bmx = -INFINITY; int bmi = 0x7FFFFFFF;
        double bs = 0.0, bq = 0.0; int bc = 0;
        #pragma unroll
        for (int j = 0; j < BPB; j += 32) {
            const int o = w * BPB + j + l;
            float pm = __ldcg(&g_pmax[o]); int pi = __ldcg(&g_pidx[o]);
            if (pm > bmx || (pm == bmx && pi < bmi)) { bmx = pm; bmi = pi; }
            bs += (double)__ldcg(&g_psum[o]);
            bq += (double)__ldcg(&g_psq[o]);
            bc += __ldcg(&g_pcnt[o]);
        }
        #pragma unroll
        for (int off = 16; off > 0; off >>= 1) {
            float om = __shfl_down_sync(FULL, bmx, off);
            int   oi = __shfl_down_sync(FULL, bmi, off);
            if (om > bmx || (om == bmx && oi < bmi)) { bmx = om; bmi = oi; }
            bs += __shfl_down_sync(FULL, bs, off);
            bq += __shfl_down_sync(FULL, bq, off);
            bc += __shfl_down_sync(FULL, bc, off);
        }
        // broadcast peak to all lanes
        bmi = __shfl_sync(FULL, bmi, 0);
        const int cy = bmi / WW, cx = bmi % WW;

        // 11x11 window correction, 121 elems over 32 lanes
        double ws = 0.0, wq = 0.0; int wc = 0;
        for (int t = l; t < (2*WIN+1)*(2*WIN+1); t += 32) {
            const int y = cy + t / (2*WIN+1) - WIN;
            const int x = cx + t % (2*WIN+1) - WIN;
            if (y >= 0 && y < HH && x >= 0 && x < WW) {
                const float v = resp[(size_t)w * NPB + (size_t)y * WW + x];
                if (v > 0.f) { ws += (double)v; wq += (double)v * (double)v; wc++; }
            }
        }
        #pragma unroll
        for (int off = 16; off > 0; off >>= 1) {
            ws += __shfl_down_sync(FULL, ws, off);
            wq += __shfl_down_sync(FULL, wq, off);
            wc += __shfl_down_sync(FULL, wc, off);
        }
        if (l == 0) {
            const double n    = (double)(bc - wc);
            const double sum  = bs - ws;
            const double sqs  = bq - wq;
            const double mean = sum / n;
            const double var  = (sqs - n * mean * mean) / (n - 1.0);
            const float  stdv = (float)sqrt(var);
            spsr[w] = (float)(((double)bmx - mean)) / (stdv + 1e-5f);
        }
    }
    __syncthreads();
    if (threadIdx.x == 0) {
        float acc = 0.f;
        #pragma unroll
        for (int i = 0; i < BATCH; i++) acc += spsr[i];
        out[0] = acc / (float)BATCH;
        g_counter = 0;   // reset for next graph replay (we're the only block left)
    }
}

extern "C" void kernel_launch(void* const* d_in, const int* in_sizes, int n_in,
                              void* d_out, int out_size) {
    const float* resp = (const float*)d_in[0];
    float* out = (float*)d_out;
    dim3 grid(BPB, BATCH);
    psr_fused<<<grid, T1>>>(resp, out);
}

// round 3
// speedup vs baseline: 1.1116x; 1.0010x over previous
#include <cuda_runtime.h>
#include <math.h>

#define HH 2048
#define WW 2048
#define NPB (HH*WW)            // 4,194,304 elems per batch
#define BATCH 8
#define BPB 128                // blocks per batch
#define T1 256                 // threads per block
#define NBLK (BPB*BATCH)       // 1024 total blocks
#define STRIDE (BPB*T1)        // 32768 threads per batch (float4 units)
#define ITERS (NPB/4/STRIDE)   // 32 float4 loads per thread, exact
#define WIN 5

// Scratch (device globals — no allocation in kernel_launch)
__device__ float g_pmax[NBLK];
__device__ int   g_pidx[NBLK];
__device__ float g_psum[NBLK];
__device__ float g_psq [NBLK];
__device__ int   g_pcnt[NBLK];
__device__ int   g_counter;      // zero-init; reset by the last block each run

__global__ void __launch_bounds__(T1) psr_fused(const float* __restrict__ resp,
                                                float* __restrict__ out) {
    const int b   = blockIdx.y;
    const int tid = blockIdx.x * T1 + threadIdx.x;       // 0..32767 within batch
    const float4* __restrict__ p = (const float4*)(resp + (size_t)b * NPB) + tid;

    float mx = -INFINITY; int mi = 0;                    // float4-granularity argmax
    float s = 0.f, sq = 0.f; int c = 0;

    #pragma unroll
    for (int kk = 0; kk < ITERS; kk += 4) {
        float4 r[4];
        #pragma unroll
        for (int j = 0; j < 4; j++)
            r[j] = p[(size_t)(kk + j) * STRIDE];         // 4 LDG.128 in flight
        #pragma unroll
        for (int j = 0; j < 4; j++) {
            const float4 v = r[j];
            // positive-sidelobe stats (branchless)
            float m;
            m = fmaxf(v.x, 0.f); s += m; sq = fmaf(m, m, sq); c += (v.x > 0.f);
            m = fmaxf(v.y, 0.f); s += m; sq = fmaf(m, m, sq); c += (v.y > 0.f);
            m = fmaxf(v.z, 0.f); s += m; sq = fmaf(m, m, sq); c += (v.z > 0.f);
            m = fmaxf(v.w, 0.f); s += m; sq = fmaf(m, m, sq); c += (v.w > 0.f);
            // coarse argmax: track best float4 only
            const float vm = fmaxf(fmaxf(v.x, v.y), fmaxf(v.z, v.w));
            if (vm > mx) { mx = vm; mi = kk + j; }       // strict > keeps first
        }
    }

    // Recover element index within the winning float4 (one reload, L2/DRAM)
    int midx;
    {
        const float4 v = __ldg(p + (size_t)mi * STRIDE);
        const int base4 = (tid + mi * STRIDE) * 4;
        int comp = 3;
        if (v.z == mx) comp = 2;
        if (v.y == mx) comp = 1;
        if (v.x == mx) comp = 0;
        midx = base4 + comp;
    }

    // ---- intra-warp reduce ----
    const unsigned FULL = 0xFFFFFFFFu;
    #pragma unroll
    for (int off = 16; off > 0; off >>= 1) {
        float om = __shfl_down_sync(FULL, mx, off);
        int   oi = __shfl_down_sync(FULL, midx, off);
        if (om > mx || (om == mx && oi < midx)) { mx = om; midx = oi; }
        s  += __shfl_down_sync(FULL, s,  off);
        sq += __shfl_down_sync(FULL, sq, off);
        c  += __shfl_down_sync(FULL, c,  off);
    }

    // ---- cross-warp reduce via smem (8 warps) ----
    __shared__ float wmax[8]; __shared__ int widx[8];
    __shared__ float wsum[8]; __shared__ float wsq[8]; __shared__ int wcnt[8];
    const int lane = threadIdx.x & 31;
    const int wid  = threadIdx.x >> 5;
    if (lane == 0) { wmax[wid] = mx; widx[wid] = midx; wsum[wid] = s; wsq[wid] = sq; wcnt[wid] = c; }
    __syncthreads();

    if (wid == 0) {
        mx   = (lane < 8) ? wmax[lane] : -INFINITY;
        midx = (lane < 8) ? widx[lane] : 0x7FFFFFFF;
        s    = (lane < 8) ? wsum[lane] : 0.f;
        sq   = (lane < 8) ? wsq[lane]  : 0.f;
        c    = (lane < 8) ? wcnt[lane] : 0;
        #pragma unroll
        for (int off = 4; off > 0; off >>= 1) {
            float om = __shfl_down_sync(FULL, mx, off);
            int   oi = __shfl_down_sync(FULL, midx, off);
            if (om > mx || (om == mx && oi < midx)) { mx = om; midx = oi; }
            s  += __shfl_down_sync(FULL, s,  off);
            sq += __shfl_down_sync(FULL, sq, off);
            c  += __shfl_down_sync(FULL, c,  off);
        }
        if (lane == 0) {
            const int o = b * BPB + blockIdx.x;
            g_pmax[o] = mx; g_pidx[o] = midx; g_psum[o] = s; g_psq[o] = sq; g_pcnt[o] = c;
        }
    }

    // ---- last-block-done: finalize in this kernel ----
    __shared__ int is_last;
    __threadfence();
    __syncthreads();
    if (threadIdx.x == 0) {
        int prev = atomicAdd(&g_counter, 1);
        is_last = (prev == NBLK - 1);
    }
    __syncthreads();
    if (!is_last) return;

    // One warp per batch (8 warps x 32 lanes).
    __shared__ float spsr[8];
    {
        const int w = threadIdx.x >> 5;     // batch
        const int l = threadIdx.x & 31;

        float bmx = -INFINITY; int bmi = 0x7FFFFFFF;
        double bs = 0.0, bq = 0.0; int bc = 0;
        #pragma unroll
        for (int j = 0; j < BPB; j += 32) {
            const int o = w * BPB + j + l;
            float pm = __ldcg(&g_pmax[o]); int pi = __ldcg(&g_pidx[o]);
            if (pm > bmx || (pm == bmx && pi < bmi)) { bmx = pm; bmi = pi; }
            bs += (double)__ldcg(&g_psum[o]);
            bq += (double)__ldcg(&g_psq[o]);
            bc += __ldcg(&g_pcnt[o]);
        }
        #pragma unroll
        for (int off = 16; off > 0; off >>= 1) {
            float om = __shfl_down_sync(FULL, bmx, off);
            int   oi = __shfl_down_sync(FULL, bmi, off);
            if (om > bmx || (om == bmx && oi < bmi)) { bmx = om; bmi = oi; }
            bs += __shfl_down_sync(FULL, bs, off);
            bq += __shfl_down_sync(FULL, bq, off);
            bc += __shfl_down_sync(FULL, bc, off);
        }
        bmi = __shfl_sync(FULL, bmi, 0);
        const int cy = bmi / WW, cx = bmi % WW;

        // 11x11 window correction, 121 elems over 32 lanes
        double ws = 0.0, wq = 0.0; int wc = 0;
        for (int t = l; t < (2*WIN+1)*(2*WIN+1); t += 32) {
            const int y = cy + t / (2*WIN+1) - WIN;
            const int x = cx + t % (2*WIN+1) - WIN;
            if (y >= 0 && y < HH && x >= 0 && x < WW) {
                const float v = resp[(size_t)w * NPB + (size_t)y * WW + x];
                if (v > 0.f) { ws += (double)v; wq += (double)v * (double)v; wc++; }
            }
        }
        #pragma unroll
        for (int off = 16; off > 0; off >>= 1) {
            ws += __shfl_down_sync(FULL, ws, off);
            wq += __shfl_down_sync(FULL, wq, off);
            wc += __shfl_down_sync(FULL, wc, off);
        }
        if (l == 0) {
            const double n    = (double)(bc - wc);
            const double sum  = bs - ws;
            const double sqs  = bq - wq;
            const double mean = sum / n;
            const double var  = (sqs - n * mean * mean) / (n - 1.0);
            const float  stdv = (float)sqrt(var);
            spsr[w] = (float)(((double)bmx - mean)) / (stdv + 1e-5f);
        }
    }
    __syncthreads();
    if (threadIdx.x == 0) {
        float acc = 0.f;
        #pragma unroll
        for (int i = 0; i < BATCH; i++) acc += spsr[i];
        out[0] = acc / (float)BATCH;
        g_counter = 0;   // only block left; safe reset for next graph replay
    }
}

extern "C" void kernel_launch(void* const* d_in, const int* in_sizes, int n_in,
                              void* d_out, int out_size) {
    const float* resp = (const float*)d_in[0];
    float* out = (float*)d_out;
    dim3 grid(BPB, BATCH);
    psr_fused<<<grid, T1>>>(resp, out);
}